// round 12
// baseline (speedup 1.0000x reference)
#include <cuda_runtime.h>
#include <cuda_fp16.h>
#include <cstdint>

// Problem constants (fixed shapes)
#define NN    50000
#define MMN   12
#define AA    64
#define BB    41
#define FF    169
#define OO    128
#define PAIRS (NN*MMN)     // 600000
#define BN_EPS 1e-5f

// ---------------- scratch (device globals) ----------------
__device__ float   d_PQ[NN * 256];                 // [n][o<128]=P, [n][128+o]=Q
__device__ __half2 d_gh[(long)PAIRS * 64];         // 153.6 MB: g as half2 (ch pairs)
__device__ float   d_ns[NN * AA];
__device__ float   d_s1[OO], d_q1[OO];
__device__ float   d_s2[AA], d_q2[AA];
__device__ float   d_p1s[64][OO], d_p1q[64][OO];   // BN1 partial slots
__device__ float   d_p2s[32][AA], d_p2q[32][AA];   // BN2 partial slots

// ---------------- packed f32x2 helpers ----------------
__device__ __forceinline__ uint64_t pk2(float lo, float hi) {
    uint64_t r; asm("mov.b64 %0, {%1, %2};" : "=l"(r) : "f"(lo), "f"(hi)); return r;
}
__device__ __forceinline__ float2 upk2(uint64_t v) {
    float2 f; asm("mov.b64 {%0, %1}, %2;" : "=f"(f.x), "=f"(f.y) : "l"(v)); return f;
}
__device__ __forceinline__ uint64_t fma2(uint64_t a, uint64_t b, uint64_t c) {
    uint64_t d; asm("fma.rn.f32x2 %0, %1, %2, %3;" : "=l"(d) : "l"(a), "l"(b), "l"(c)); return d;
}
__device__ __forceinline__ uint64_t add2(uint64_t a, uint64_t b) {
    uint64_t d; asm("add.rn.f32x2 %0, %1, %2;" : "=l"(d) : "l"(a), "l"(b)); return d;
}
__device__ __forceinline__ float tanh_ap(float x) {
    float y; asm("tanh.approx.f32 %0, %1;" : "=f"(y) : "f"(x)); return y;
}
__device__ __forceinline__ uint32_t smem_u32(const void* p) {
    uint32_t a;
    asm("{ .reg .u64 t; cvta.to.shared.u64 t, %1; cvt.u32.u64 %0, t; }" : "=r"(a) : "l"(p));
    return a;
}

// ---------------- K0: zero partial-stat slots ----------------
__global__ void kzero() {
    int i = blockIdx.x * blockDim.x + threadIdx.x;
    if (i < 64 * OO) { (&d_p1s[0][0])[i] = 0.f; (&d_p1q[0][0])[i] = 0.f; }
    if (i < 32 * AA) { (&d_p2s[0][0])[i] = 0.f; (&d_p2q[0][0])[i] = 0.f; }
}

// ---------------- K1: PQ = atom @ [W1;W2]^T  (N x 256, K=64) ----------------
__global__ __launch_bounds__(256) void k_pq(const float* __restrict__ atom,
                                            const float* __restrict__ W) {
    __shared__ __align__(16) float As[64 * 64];
    int t  = threadIdx.x;
    int o  = t & 127;
    int f0 = (t >> 7) * 64;

    float w[64];
#pragma unroll
    for (int k = 0; k < 64; k++) w[k] = W[o * FF + f0 + k];

    int row0  = blockIdx.x * 64;
    int nrows = NN - row0; if (nrows > 64) nrows = 64;

    for (int i = t; i < nrows * 64; i += 256) As[i] = atom[row0 * 64 + i];
    __syncthreads();

    for (int r = 0; r < nrows; r++) {
        const float4* ap = (const float4*)&As[r * 64];
        float a0 = 0.f, a1 = 0.f;
#pragma unroll
        for (int k4 = 0; k4 < 16; k4++) {
            float4 v = ap[k4];
            a0 += v.x * w[k4 * 4 + 0] + v.z * w[k4 * 4 + 2];
            a1 += v.y * w[k4 * 4 + 1] + v.w * w[k4 * 4 + 3];
        }
        d_PQ[(row0 + r) * 256 + t] = a0 + a1;
    }
}

// ---------------- K2: main pass (packed FFMA2) ----------------
// Thread owns channel pair (2u, 2u+1); grp = t>>6 handles pairs {2g, 2g+1} of
// each 8-pair batch. x staged DUPLICATED in smem so ld.shared.v2.b64 yields
// packed f32x2 operands with no mov.b64 in the hot loop.
#define PPB2  240
#define GRID2 2500
__global__ __launch_bounds__(256, 2) void k_main(const float* __restrict__ nbr,
                                                 const int*   __restrict__ idx,
                                                 const float* __restrict__ W,
                                                 const float* __restrict__ b) {
    __shared__ __align__(16) float2 nsd[8 * 44];   // duplicated x, k padded to 44
    __shared__ int is[8];
    int t = threadIdx.x;
    int u = t & 63, grp = t >> 6;
    int c0 = 2 * u;

    uint64_t w2[42];
#pragma unroll
    for (int k = 0; k < 42; k++)
        w2[k] = (k < BB) ? pk2(W[c0 * FF + 128 + k], W[(c0 + 1) * FF + 128 + k]) : 0ull;
    uint64_t b2 = pk2(b[c0], b[c0 + 1]);

    // zero pad slots k=41..43 (never rewritten)
    for (int i = t; i < 8 * 3; i += 256) {
        int pp = i / 3, kk = 41 + i % 3;
        nsd[pp * 44 + kk] = make_float2(0.f, 0.f);
    }

    uint32_t nsb = smem_u32(nsd);
    int pbase = blockIdx.x * PPB2;
    uint64_t ls2 = 0ull, lq2 = 0ull;

    for (int gi = 0; gi < PPB2 / 8; gi++) {
        int gb = pbase + gi * 8;
        __syncthreads();
        for (int i = t; i < 8 * BB; i += 256) {
            int pp = i / BB, kk = i - pp * BB;
            float x = nbr[(long)gb * BB + i];
            nsd[pp * 44 + kk] = make_float2(x, x);
        }
        if (t < 8) is[t] = idx[gb + t];
        __syncthreads();

#pragma unroll
        for (int pq = 0; pq < 2; pq++) {
            int pp = grp * 2 + pq;
            int pi = gb + pp;
            int n  = pi / 12;
            int j  = is[pp];
            uint64_t a0 = 0ull, a1 = 0ull;
            uint32_t base = nsb + pp * 352;
#pragma unroll
            for (int k2 = 0; k2 < 21; k2++) {
                uint64_t xa, xb;
                asm volatile("ld.shared.v2.b64 {%0, %1}, [%2];"
                             : "=l"(xa), "=l"(xb) : "r"(base + k2 * 16));
                a0 = fma2(w2[2 * k2],     xa, a0);
                a1 = fma2(w2[2 * k2 + 1], xb, a1);
            }
            uint64_t P2 = *(const uint64_t*)&d_PQ[n * 256 + c0];
            uint64_t Q2 = *(const uint64_t*)&d_PQ[j * 256 + 128 + c0];
            uint64_t gv = add2(add2(a0, a1), add2(add2(P2, Q2), b2));
            float2 g = upk2(gv);
            d_gh[(long)pi * 64 + u] = __floats2half2_rn(g.x, g.y);
            ls2 = add2(ls2, gv);
            lq2 = fma2(gv, gv, lq2);
        }
    }
    float2 s = upk2(ls2), q = upk2(lq2);
    int slot = blockIdx.x & 63;
    atomicAdd(&d_p1s[slot][c0],     s.x);
    atomicAdd(&d_p1s[slot][c0 + 1], s.y);
    atomicAdd(&d_p1q[slot][c0],     q.x);
    atomicAdd(&d_p1q[slot][c0 + 1], q.y);
}

// ---------------- K3: finalize BN1 stats ----------------
__global__ void k_fin1() {
    int t = threadIdx.x;
    if (t < OO) {
        float s = 0.f, q = 0.f;
#pragma unroll
        for (int i = 0; i < 64; i++) { s += d_p1s[i][t]; q += d_p1q[i][t]; }
        d_s1[t] = s; d_q1[t] = q;
    }
}

// ---------------- K4: BN1 + sigmoid*softplus + sum over m + BN2 partials ----
#define GRID4 1480
__global__ __launch_bounds__(256) void k_reduce(const float* __restrict__ g1,
                                                const float* __restrict__ b1) {
    int t = threadIdx.x;
    int u = t & 31, sub = t >> 5;           // 8 n-slots per block
    int a0 = 2 * u;

    float inv = 1.f / (float)PAIRS;
    float mf0 = d_s1[a0] * inv,      mf1 = d_s1[a0 + 1] * inv;
    float vf0 = d_q1[a0] * inv - mf0 * mf0;
    float vf1 = d_q1[a0 + 1] * inv - mf1 * mf1;
    float sf0 = rsqrtf(vf0 + BN_EPS) * g1[a0];
    float sf1 = rsqrtf(vf1 + BN_EPS) * g1[a0 + 1];
    float tf0 = b1[a0] - mf0 * sf0,  tf1 = b1[a0 + 1] - mf1 * sf1;

    float mc0 = d_s1[64 + a0] * inv, mc1 = d_s1[65 + a0] * inv;
    float vc0 = d_q1[64 + a0] * inv - mc0 * mc0;
    float vc1 = d_q1[65 + a0] * inv - mc1 * mc1;
    float sc0 = rsqrtf(vc0 + BN_EPS) * g1[64 + a0];
    float sc1 = rsqrtf(vc1 + BN_EPS) * g1[65 + a0];
    float tc0 = b1[64 + a0] - mc0 * sc0, tc1 = b1[65 + a0] - mc1 * sc1;

    float ls0 = 0.f, ls1 = 0.f, lq0 = 0.f, lq1 = 0.f;
    for (int n = blockIdx.x * 8 + sub; n < NN; n += gridDim.x * 8) {
        const __half2* gp = &d_gh[(long)n * 12 * 64];
        float acc0 = 0.f, acc1 = 0.f;
#pragma unroll
        for (int m = 0; m < 12; m++) {
            float2 xf = __half22float2(gp[m * 64 + u]);
            float2 xc = __half22float2(gp[m * 64 + 32 + u]);
            float f0 = xf.x * sf0 + tf0, f1 = xf.y * sf1 + tf1;
            float c0v = xc.x * sc0 + tc0, c1v = xc.y * sc1 + tc1;
            float sg0 = 0.5f * tanh_ap(0.5f * f0) + 0.5f;
            float sg1 = 0.5f * tanh_ap(0.5f * f1) + 0.5f;
            float sp0 = fmaxf(c0v, 0.f) + __logf(1.f + __expf(-fabsf(c0v)));
            float sp1 = fmaxf(c1v, 0.f) + __logf(1.f + __expf(-fabsf(c1v)));
            acc0 += sg0 * sp0;
            acc1 += sg1 * sp1;
        }
        *(float2*)&d_ns[n * 64 + a0] = make_float2(acc0, acc1);
        ls0 += acc0; lq0 += acc0 * acc0;
        ls1 += acc1; lq1 += acc1 * acc1;
    }
    int slot = blockIdx.x & 31;
    atomicAdd(&d_p2s[slot][a0],     ls0);
    atomicAdd(&d_p2s[slot][a0 + 1], ls1);
    atomicAdd(&d_p2q[slot][a0],     lq0);
    atomicAdd(&d_p2q[slot][a0 + 1], lq1);
}

// ---------------- K5: finalize BN2 stats ----------------
__global__ void k_fin2() {
    int t = threadIdx.x;
    if (t < AA) {
        float s = 0.f, q = 0.f;
#pragma unroll
        for (int i = 0; i < 32; i++) { s += d_p2s[i][t]; q += d_p2q[i][t]; }
        d_s2[t] = s; d_q2[t] = q;
    }
}

// ---------------- K6: BN2 + residual + softplus -> out ----------------------
__global__ __launch_bounds__(256) void k_out(const float* __restrict__ atom,
                                             const float* __restrict__ g2,
                                             const float* __restrict__ b2,
                                             float* __restrict__ out) {
    int i = blockIdx.x * blockDim.x + threadIdx.x;
    if (i >= NN * 64) return;
    int a = i & 63;
    float inv = 1.f / (float)NN;
    float m = d_s2[a] * inv;
    float v = d_q2[a] * inv - m * m;
    float s = rsqrtf(v + BN_EPS) * g2[a];
    float tt = b2[a] - m * s;
    float x = atom[i] + d_ns[i] * s + tt;
    out[i] = fmaxf(x, 0.f) + __logf(1.f + __expf(-fabsf(x)));
}

// ---------------- launch ------------------------------------------------------
extern "C" void kernel_launch(void* const* d_in, const int* in_sizes, int n_in,
                              void* d_out, int out_size) {
    const float* atom = (const float*)d_in[0];   // (N, 64)
    const float* nbr  = (const float*)d_in[1];   // (N, 12, 41)
    const int*   idx  = (const int*)  d_in[2];   // (N, 12)
    const float* W    = (const float*)d_in[3];   // (128, 169)
    const float* b    = (const float*)d_in[4];   // (128,)
    const float* g1   = (const float*)d_in[5];
    const float* b1   = (const float*)d_in[6];
    const float* g2   = (const float*)d_in[7];
    const float* b2   = (const float*)d_in[8];
    float* out = (float*)d_out;

    kzero   <<<16, 512>>>();
    k_pq    <<<(NN + 63) / 64, 256>>>(atom, W);
    k_main  <<<GRID2, 256>>>(nbr, idx, W, b);
    k_fin1  <<<1, 128>>>();
    k_reduce<<<GRID4, 256>>>(g1, b1);
    k_fin2  <<<1, 64>>>();
    k_out   <<<(NN * 64 + 255) / 256, 256>>>(atom, g2, b2, out);
}

// round 15
// speedup vs baseline: 2.1335x; 2.1335x over previous
#include <cuda_runtime.h>
#include <cuda_fp16.h>
#include <cstdint>

// Problem constants (fixed shapes)
#define NN    50000
#define MMN   12
#define AA    64
#define BB    41
#define FF    169
#define OO    128
#define PAIRS (NN*MMN)     // 600000
#define BN_EPS 1e-5f

#define XSTR  56           // smem row stride in halfs: 112B, 16B-aligned rows for ldmatrix
#define TPB   4            // tiles (128 pairs) per block
#define GRIDM 1172         // 1172*4 = 4688 tiles >= ceil(600000/128)

// ---------------- scratch (device globals; 16B-aligned for vector access) ----
__device__ __align__(16) float   d_PQ[NN * 256];               // [n][o<128]=P, [n][128+o]=Q
__device__ __align__(16) __half2 d_gh[(long)PAIRS * 64];       // g as half2 (channel pairs)
__device__ __align__(16) float   d_ns[NN * AA];
__device__ __align__(16) float   d_s1[OO], d_q1[OO];
__device__ __align__(16) float   d_s2[AA], d_q2[AA];
__device__ __align__(16) float   d_p1s[64][OO], d_p1q[64][OO]; // BN1 partial slots
__device__ __align__(16) float   d_p2s[32][AA], d_p2q[32][AA]; // BN2 partial slots
__device__ __align__(16) uint2   d_Bf[3 * 16 * 32];            // W3 B-fragments, lane-indexed

// ---------------- helpers ----------------
__device__ __forceinline__ float tanh_ap(float x) {
    float y; asm("tanh.approx.f32 %0, %1;" : "=f"(y) : "f"(x)); return y;
}
__device__ __forceinline__ uint32_t smem_u32(const void* p) {
    uint32_t a;
    asm("{ .reg .u64 t; cvta.to.shared.u64 t, %1; cvt.u32.u64 %0, t; }" : "=r"(a) : "l"(p));
    return a;
}

// ---------------- K0: zero partial-stat slots ----------------
__global__ void kzero() {
    int i = blockIdx.x * blockDim.x + threadIdx.x;
    if (i < 64 * OO) { (&d_p1s[0][0])[i] = 0.f; (&d_p1q[0][0])[i] = 0.f; }
    if (i < 32 * AA) { (&d_p2s[0][0])[i] = 0.f; (&d_p2q[0][0])[i] = 0.f; }
}

// ---------------- K0b: build W3 B-fragments (once, tiny) ----------------
// mma.m16n8k16 B frag (col-major B): lane (g=lane>>2, t=lane&3):
//   b0 = {B[2t][g], B[2t+1][g]},  b1 = {B[2t+8][g], B[2t+9][g]},  B[k][n] = W3[n][k]
__global__ void k_bfrag(const float* __restrict__ W) {
    int e = blockIdx.x * blockDim.x + threadIdx.x;
    if (e >= 3 * 16 * 32) return;
    int lane = e & 31, nt = (e >> 5) & 15, ks = e >> 9;
    int g = lane >> 2, tq = lane & 3;
    int ch = nt * 8 + g;
    int k0 = ks * 16 + 2 * tq;
    float w0 = (k0     < BB) ? W[ch * FF + 128 + k0]     : 0.f;
    float w1 = (k0 + 1 < BB) ? W[ch * FF + 128 + k0 + 1] : 0.f;
    float w8 = (k0 + 8 < BB) ? W[ch * FF + 128 + k0 + 8] : 0.f;
    float w9 = (k0 + 9 < BB) ? W[ch * FF + 128 + k0 + 9] : 0.f;
    __half2 b01 = __floats2half2_rn(w0, w1);
    __half2 b23 = __floats2half2_rn(w8, w9);
    uint2 v;
    v.x = *reinterpret_cast<uint32_t*>(&b01);
    v.y = *reinterpret_cast<uint32_t*>(&b23);
    d_Bf[e] = v;
}

// ---------------- K1: PQ = atom @ [W1;W2]^T  (N x 256, K=64) ----------------
__global__ __launch_bounds__(256) void k_pq(const float* __restrict__ atom,
                                            const float* __restrict__ W) {
    __shared__ __align__(16) float As[64 * 64];
    int t  = threadIdx.x;
    int o  = t & 127;
    int f0 = (t >> 7) * 64;

    float w[64];
#pragma unroll
    for (int k = 0; k < 64; k++) w[k] = W[o * FF + f0 + k];

    int row0  = blockIdx.x * 64;
    int nrows = NN - row0; if (nrows > 64) nrows = 64;

    for (int i = t; i < nrows * 64; i += 256) As[i] = atom[row0 * 64 + i];
    __syncthreads();

    for (int r = 0; r < nrows; r++) {
        const float4* ap = (const float4*)&As[r * 64];
        float a0 = 0.f, a1 = 0.f;
#pragma unroll
        for (int k4 = 0; k4 < 16; k4++) {
            float4 v = ap[k4];
            a0 += v.x * w[k4 * 4 + 0] + v.z * w[k4 * 4 + 2];
            a1 += v.y * w[k4 * 4 + 1] + v.w * w[k4 * 4 + 3];
        }
        d_PQ[(row0 + r) * 256 + t] = a0 + a1;
    }
}

// ---------------- K2: main GEMM via mma.sync (HMMA) + gather epilogue ------
// Tile = 128 pairs x 128 channels. 8 warps; warp w owns pairs [w*16, w*16+16).
// A: x staged fp16 in smem, loaded via ldmatrix.x4 (3 k-steps).
// B: precomputed lane-indexed fragments from d_Bf (L1-resident, LDG.64).
__global__ __launch_bounds__(256) void k_main(const float* __restrict__ nbr,
                                              const int*   __restrict__ idx,
                                              const float* __restrict__ b) {
    __shared__ __align__(16) __half XS[128 * XSTR];
    __shared__ __align__(16) float b_s[128];
    int t = threadIdx.x, w = t >> 5, lane = t & 31;
    int g = lane >> 2, tq = lane & 3;

    if (t < 128) b_s[t] = b[t];
    // zero pad columns k=41..55 once (never overwritten)
    for (int i = t; i < 128 * (XSTR - BB); i += 256) {
        int r = i / (XSTR - BB), k = BB + (i - r * (XSTR - BB));
        XS[r * XSTR + k] = __float2half(0.f);
    }

    uint32_t xsb = smem_u32(XS);
    int rrow = w * 16 + (lane & 15);
    int coff = (lane >> 4) * 8;

    for (int ti = 0; ti < TPB; ti++) {
        int tile = blockIdx.x * TPB + ti;
        int p0 = tile * 128;
        __syncthreads();
        // stage x tile: 128 pairs x 41 f32 -> fp16 smem (coalesced reads)
        for (int e = t; e < 128 * BB; e += 256) {
            int r = e / BB, k = e - r * BB;
            long gi = (long)p0 * BB + e;
            float v = (gi < (long)PAIRS * BB) ? nbr[gi] : 0.f;
            XS[r * XSTR + k] = __float2half_rn(v);
        }
        __syncthreads();

        // A fragments for this warp's 16 pairs (3 k-steps of 16)
        uint32_t a[3][4];
#pragma unroll
        for (int ks = 0; ks < 3; ks++) {
            uint32_t addr = xsb + (uint32_t)(rrow * XSTR + ks * 16 + coff) * 2;
            asm volatile("ldmatrix.sync.aligned.m8n8.x4.shared.b16 {%0,%1,%2,%3}, [%4];"
                         : "=r"(a[ks][0]), "=r"(a[ks][1]), "=r"(a[ks][2]), "=r"(a[ks][3])
                         : "r"(addr));
        }

        int pi0 = p0 + w * 16 + g;
        int pi1 = pi0 + 8;
        bool v0 = pi0 < PAIRS, v1 = pi1 < PAIRS;
        int j0 = v0 ? idx[pi0] : 0;
        int j1 = v1 ? idx[pi1] : 0;
        int n0 = (v0 ? pi0 : PAIRS - 1) / MMN;
        int n1 = (v1 ? pi1 : PAIRS - 1) / MMN;
        const float* P0 = &d_PQ[n0 * 256];
        const float* P1 = &d_PQ[n1 * 256];
        const float* Q0 = &d_PQ[j0 * 256 + 128];
        const float* Q1 = &d_PQ[j1 * 256 + 128];

#pragma unroll 4
        for (int nt = 0; nt < 16; nt++) {
            float c0 = 0.f, c1 = 0.f, c2 = 0.f, c3 = 0.f;
#pragma unroll
            for (int ks = 0; ks < 3; ks++) {
                uint2 bf = d_Bf[(ks * 16 + nt) * 32 + lane];
                asm volatile(
                    "mma.sync.aligned.m16n8k16.row.col.f32.f16.f16.f32 "
                    "{%0,%1,%2,%3}, {%4,%5,%6,%7}, {%8,%9}, {%0,%1,%2,%3};"
                    : "+f"(c0), "+f"(c1), "+f"(c2), "+f"(c3)
                    : "r"(a[ks][0]), "r"(a[ks][1]), "r"(a[ks][2]), "r"(a[ks][3]),
                      "r"(bf.x), "r"(bf.y));
            }
            int ch = nt * 8 + 2 * tq;                // even channel of this lane's pair
            float2 bv  = *(const float2*)&b_s[ch];
            float2 p0v = *(const float2*)&P0[ch];
            float2 q0v = *(const float2*)&Q0[ch];
            float2 p1v = *(const float2*)&P1[ch];
            float2 q1v = *(const float2*)&Q1[ch];
            float g00 = c0 + p0v.x + q0v.x + bv.x;
            float g01 = c1 + p0v.y + q0v.y + bv.y;
            float g10 = c2 + p1v.x + q1v.x + bv.x;
            float g11 = c3 + p1v.y + q1v.y + bv.y;
            if (v0) d_gh[(long)pi0 * 64 + nt * 4 + tq] = __floats2half2_rn(g00, g01);
            if (v1) d_gh[(long)pi1 * 64 + nt * 4 + tq] = __floats2half2_rn(g10, g11);
        }
    }
}

// ---------------- K3: BN1 stats pass over d_gh ----------------
#define GRIDS 1184
__global__ __launch_bounds__(256) void k_stats() {
    int t = threadIdx.x;
    int u = t & 63, sub = t >> 6;
    float s0 = 0.f, s1 = 0.f, q0 = 0.f, q1 = 0.f;
    for (long pi = blockIdx.x * 4 + sub; pi < PAIRS; pi += (long)gridDim.x * 4) {
        float2 v = __half22float2(d_gh[pi * 64 + u]);
        s0 += v.x; s1 += v.y;
        q0 += v.x * v.x; q1 += v.y * v.y;
    }
    int slot = blockIdx.x & 63;
    int c0 = 2 * u;
    atomicAdd(&d_p1s[slot][c0],     s0);
    atomicAdd(&d_p1s[slot][c0 + 1], s1);
    atomicAdd(&d_p1q[slot][c0],     q0);
    atomicAdd(&d_p1q[slot][c0 + 1], q1);
}

// ---------------- K3b: finalize BN1 stats ----------------
__global__ void k_fin1() {
    int t = threadIdx.x;                 // 256
    int ch = t >> 1, h = t & 1;
    float s = 0.f, q = 0.f;
#pragma unroll
    for (int i = 0; i < 32; i++) { s += d_p1s[h * 32 + i][ch]; q += d_p1q[h * 32 + i][ch]; }
    s += __shfl_xor_sync(0xffffffffu, s, 1);
    q += __shfl_xor_sync(0xffffffffu, q, 1);
    if (!h) { d_s1[ch] = s; d_q1[ch] = q; }
}

// ---------------- K4: BN1 + sigmoid*softplus + sum over m + BN2 partials ----
#define GRID4 1480
__global__ __launch_bounds__(256) void k_reduce(const float* __restrict__ g1,
                                                const float* __restrict__ b1) {
    int t = threadIdx.x;
    int u = t & 31, sub = t >> 5;
    int a0 = 2 * u;

    float inv = 1.f / (float)PAIRS;
    float mf0 = d_s1[a0] * inv,      mf1 = d_s1[a0 + 1] * inv;
    float vf0 = d_q1[a0] * inv - mf0 * mf0;
    float vf1 = d_q1[a0 + 1] * inv - mf1 * mf1;
    float sf0 = rsqrtf(vf0 + BN_EPS) * g1[a0];
    float sf1 = rsqrtf(vf1 + BN_EPS) * g1[a0 + 1];
    float tf0 = b1[a0] - mf0 * sf0,  tf1 = b1[a0 + 1] - mf1 * sf1;

    float mc0 = d_s1[64 + a0] * inv, mc1 = d_s1[65 + a0] * inv;
    float vc0 = d_q1[64 + a0] * inv - mc0 * mc0;
    float vc1 = d_q1[65 + a0] * inv - mc1 * mc1;
    float sc0 = rsqrtf(vc0 + BN_EPS) * g1[64 + a0];
    float sc1 = rsqrtf(vc1 + BN_EPS) * g1[65 + a0];
    float tc0 = b1[64 + a0] - mc0 * sc0, tc1 = b1[65 + a0] - mc1 * sc1;

    float ls0 = 0.f, ls1 = 0.f, lq0 = 0.f, lq1 = 0.f;
    for (int n = blockIdx.x * 8 + sub; n < NN; n += gridDim.x * 8) {
        const __half2* gp = &d_gh[(long)n * 12 * 64];
        float acc0 = 0.f, acc1 = 0.f;
#pragma unroll
        for (int m = 0; m < 12; m++) {
            float2 xf = __half22float2(gp[m * 64 + u]);
            float2 xc = __half22float2(gp[m * 64 + 32 + u]);
            float f0 = xf.x * sf0 + tf0, f1 = xf.y * sf1 + tf1;
            float c0v = xc.x * sc0 + tc0, c1v = xc.y * sc1 + tc1;
            float sg0 = 0.5f * tanh_ap(0.5f * f0) + 0.5f;
            float sg1 = 0.5f * tanh_ap(0.5f * f1) + 0.5f;
            float sp0 = fmaxf(c0v, 0.f) + __logf(1.f + __expf(-fabsf(c0v)));
            float sp1 = fmaxf(c1v, 0.f) + __logf(1.f + __expf(-fabsf(c1v)));
            acc0 += sg0 * sp0;
            acc1 += sg1 * sp1;
        }
        *(float2*)&d_ns[n * 64 + a0] = make_float2(acc0, acc1);
        ls0 += acc0; lq0 += acc0 * acc0;
        ls1 += acc1; lq1 += acc1 * acc1;
    }
    int slot = blockIdx.x & 31;
    atomicAdd(&d_p2s[slot][a0],     ls0);
    atomicAdd(&d_p2s[slot][a0 + 1], ls1);
    atomicAdd(&d_p2q[slot][a0],     lq0);
    atomicAdd(&d_p2q[slot][a0 + 1], lq1);
}

// ---------------- K5: finalize BN2 stats ----------------
__global__ void k_fin2() {
    int t = threadIdx.x;                 // 256
    int ch = t >> 2, qd = t & 3;
    float s = 0.f, q = 0.f;
#pragma unroll
    for (int i = 0; i < 8; i++) { s += d_p2s[qd * 8 + i][ch]; q += d_p2q[qd * 8 + i][ch]; }
    s += __shfl_xor_sync(0xffffffffu, s, 1);
    q += __shfl_xor_sync(0xffffffffu, q, 1);
    s += __shfl_xor_sync(0xffffffffu, s, 2);
    q += __shfl_xor_sync(0xffffffffu, q, 2);
    if (qd == 0) { d_s2[ch] = s; d_q2[ch] = q; }
}

// ---------------- K6: BN2 + residual + softplus -> out ----------------------
__global__ __launch_bounds__(256) void k_out(const float* __restrict__ atom,
                                             const float* __restrict__ g2,
                                             const float* __restrict__ b2,
                                             float* __restrict__ out) {
    int i = blockIdx.x * blockDim.x + threadIdx.x;
    if (i >= NN * 64) return;
    int a = i & 63;
    float inv = 1.f / (float)NN;
    float m = d_s2[a] * inv;
    float v = d_q2[a] * inv - m * m;
    float s = rsqrtf(v + BN_EPS) * g2[a];
    float tt = b2[a] - m * s;
    float x = atom[i] + d_ns[i] * s + tt;
    out[i] = fmaxf(x, 0.f) + __logf(1.f + __expf(-fabsf(x)));
}

// ---------------- launch ------------------------------------------------------
extern "C" void kernel_launch(void* const* d_in, const int* in_sizes, int n_in,
                              void* d_out, int out_size) {
    const float* atom = (const float*)d_in[0];   // (N, 64)
    const float* nbr  = (const float*)d_in[1];   // (N, 12, 41)
    const int*   idx  = (const int*)  d_in[2];   // (N, 12)
    const float* W    = (const float*)d_in[3];   // (128, 169)
    const float* b    = (const float*)d_in[4];   // (128,)
    const float* g1   = (const float*)d_in[5];
    const float* b1   = (const float*)d_in[6];
    const float* g2   = (const float*)d_in[7];
    const float* b2   = (const float*)d_in[8];
    float* out = (float*)d_out;

    kzero   <<<16, 512>>>();
    k_bfrag <<<6, 256>>>(W);
    k_pq    <<<(NN + 63) / 64, 256>>>(atom, W);
    k_main  <<<GRIDM, 256>>>(nbr, idx, b);
    k_stats <<<GRIDS, 256>>>();
    k_fin1  <<<1, 256>>>();
    k_reduce<<<GRID4, 256>>>(g1, b1);
    k_fin2  <<<1, 256>>>();
    k_out   <<<(NN * 64 + 255) / 256, 256>>>(atom, g2, b2, out);
}

// round 16
// speedup vs baseline: 2.2094x; 1.0356x over previous
#include <cuda_runtime.h>
#include <cuda_fp16.h>
#include <cstdint>

// Problem constants (fixed shapes)
#define NN    50000
#define MMN   12
#define AA    64
#define BB    41
#define FF    169
#define OO    128
#define PAIRS (NN*MMN)     // 600000
#define BN_EPS 1e-5f

#define XSTR  56           // smem row stride in halfs (112B, 16B-aligned rows)
#define TPB   4            // tiles (128 pairs) per block
#define GRIDM 1172         // 1172*4 = 4688 tiles >= ceil(600000/128)

// dynamic smem layout for k_main (bytes)
#define SM_XS   0                       // 128*56 halfs        = 14336
#define SM_GO   14336                   // 128*132 f32         = 67584
#define SM_PS   81920                   // 12*132 f32          = 6336
#define SM_BS   88256                   // 128 f32             = 512
#define SM_JS   88768                   // 128 int             = 512
#define SM_TOT  89280

// ---------------- scratch (device globals) ----------------
__device__ __align__(16) float   d_PQ[NN * 256];               // [n][o<128]=P, [n][128+o]=Q
__device__ __align__(16) __half2 d_gh[(long)PAIRS * 64];       // g as half2 (channel pairs)
__device__ __align__(16) float   d_ns[NN * AA];
__device__ __align__(16) float   d_s1[OO], d_q1[OO];
__device__ __align__(16) float   d_s2[AA], d_q2[AA];
__device__ __align__(16) float   d_p1s[64][OO], d_p1q[64][OO]; // BN1 partial slots
__device__ __align__(16) float   d_p2s[32][AA], d_p2q[32][AA]; // BN2 partial slots
__device__ __align__(16) uint2   d_Bf[3 * 16 * 32];            // W3 B-fragments (k_main)
__device__ __align__(16) uint2   d_Bf2[4 * 32 * 32];           // W12 B-fragments (k_pq)

// ---------------- helpers ----------------
__device__ __forceinline__ float tanh_ap(float x) {
    float y; asm("tanh.approx.f32 %0, %1;" : "=f"(y) : "f"(x)); return y;
}
__device__ __forceinline__ uint32_t smem_u32(const void* p) {
    uint32_t a;
    asm("{ .reg .u64 t; cvta.to.shared.u64 t, %1; cvt.u32.u64 %0, t; }" : "=r"(a) : "l"(p));
    return a;
}

// ---------------- K0: zero partial-stat slots ----------------
__global__ void kzero() {
    int i = blockIdx.x * blockDim.x + threadIdx.x;
    if (i < 64 * OO) { (&d_p1s[0][0])[i] = 0.f; (&d_p1q[0][0])[i] = 0.f; }
    if (i < 32 * AA) { (&d_p2s[0][0])[i] = 0.f; (&d_p2q[0][0])[i] = 0.f; }
}

// ---------------- K0b: W3 B-fragments (nbr GEMM), lane-indexed --------------
__global__ void k_bfrag(const float* __restrict__ W) {
    int e = blockIdx.x * blockDim.x + threadIdx.x;
    if (e >= 3 * 16 * 32) return;
    int lane = e & 31, nt = (e >> 5) & 15, ks = e >> 9;
    int g = lane >> 2, tq = lane & 3;
    int ch = nt * 8 + g;
    int k0 = ks * 16 + 2 * tq;
    float w0 = (k0     < BB) ? W[ch * FF + 128 + k0]     : 0.f;
    float w1 = (k0 + 1 < BB) ? W[ch * FF + 128 + k0 + 1] : 0.f;
    float w8 = (k0 + 8 < BB) ? W[ch * FF + 128 + k0 + 8] : 0.f;
    float w9 = (k0 + 9 < BB) ? W[ch * FF + 128 + k0 + 9] : 0.f;
    __half2 b01 = __floats2half2_rn(w0, w1);
    __half2 b23 = __floats2half2_rn(w8, w9);
    uint2 v;
    v.x = *reinterpret_cast<uint32_t*>(&b01);
    v.y = *reinterpret_cast<uint32_t*>(&b23);
    d_Bf[e] = v;
}

// ---------------- K0c: W12 B-fragments (PQ GEMM, N=256, K=64) ---------------
// B[k][n] = (n<128) ? W[n][k] : W[n-128][64+k]
__global__ void k_bfrag2(const float* __restrict__ W) {
    int e = blockIdx.x * blockDim.x + threadIdx.x;
    if (e >= 4 * 32 * 32) return;
    int lane = e & 31, nt = (e >> 5) & 31, ks = e >> 10;
    int g = lane >> 2, tq = lane & 3;
    int n = nt * 8 + g;
    int k0 = ks * 16 + 2 * tq;
    const float* src = (n < 128) ? &W[n * FF] : &W[(n - 128) * FF + 64];
    __half2 b01 = __floats2half2_rn(src[k0],     src[k0 + 1]);
    __half2 b23 = __floats2half2_rn(src[k0 + 8], src[k0 + 9]);
    uint2 v;
    v.x = *reinterpret_cast<uint32_t*>(&b01);
    v.y = *reinterpret_cast<uint32_t*>(&b23);
    d_Bf2[e] = v;
}

// ---------------- K1: PQ = atom @ [W1;W2]^T via HMMA (N x 256, K=64) --------
#define ASTR 72   // 144B rows, 16B-aligned
__global__ __launch_bounds__(256) void k_pq(const float* __restrict__ atom) {
    __shared__ __align__(16) __half AS[128 * ASTR];
    int t = threadIdx.x, w = t >> 5, lane = t & 31;
    int g = lane >> 2, tq = lane & 3;
    int row0 = blockIdx.x * 128;

    for (int e = t; e < 128 * 64; e += 256) {
        int r = e >> 6, k = e & 63;
        float v = (row0 + r < NN) ? atom[(row0 + r) * 64 + k] : 0.f;
        AS[r * ASTR + k] = __float2half_rn(v);
    }
    __syncthreads();

    uint32_t asb = smem_u32(AS);
    int rrow = w * 16 + (lane & 15);
    int coff = (lane >> 4) * 8;

    uint32_t a[4][4];
#pragma unroll
    for (int ks = 0; ks < 4; ks++) {
        uint32_t addr = asb + (uint32_t)(rrow * ASTR + ks * 16 + coff) * 2;
        asm volatile("ldmatrix.sync.aligned.m8n8.x4.shared.b16 {%0,%1,%2,%3}, [%4];"
                     : "=r"(a[ks][0]), "=r"(a[ks][1]), "=r"(a[ks][2]), "=r"(a[ks][3])
                     : "r"(addr));
    }

    int r0 = row0 + w * 16 + g;
    int r1 = r0 + 8;
#pragma unroll 4
    for (int nt = 0; nt < 32; nt++) {
        float c0 = 0.f, c1 = 0.f, c2 = 0.f, c3 = 0.f;
#pragma unroll
        for (int ks = 0; ks < 4; ks++) {
            uint2 bf = d_Bf2[(ks * 32 + nt) * 32 + lane];
            asm volatile(
                "mma.sync.aligned.m16n8k16.row.col.f32.f16.f16.f32 "
                "{%0,%1,%2,%3}, {%4,%5,%6,%7}, {%8,%9}, {%0,%1,%2,%3};"
                : "+f"(c0), "+f"(c1), "+f"(c2), "+f"(c3)
                : "r"(a[ks][0]), "r"(a[ks][1]), "r"(a[ks][2]), "r"(a[ks][3]),
                  "r"(bf.x), "r"(bf.y));
        }
        int ch = nt * 8 + 2 * tq;
        if (r0 < NN) *(float2*)&d_PQ[r0 * 256 + ch] = make_float2(c0, c1);
        if (r1 < NN) *(float2*)&d_PQ[r1 * 256 + ch] = make_float2(c2, c3);
    }
}

// ---------------- K2: main GEMM (HMMA) + coalesced epilogue + BN1 stats -----
__global__ __launch_bounds__(256) void k_main(const float* __restrict__ nbr,
                                              const int*   __restrict__ idx,
                                              const float* __restrict__ b) {
    extern __shared__ __align__(16) char smem[];
    __half* XS  = (__half*)(smem + SM_XS);
    float*  GO  = (float*) (smem + SM_GO);
    float*  PS  = (float*) (smem + SM_PS);
    float*  BS  = (float*) (smem + SM_BS);
    int*    JS  = (int*)   (smem + SM_JS);

    int t = threadIdx.x, w = t >> 5, lane = t & 31;
    int g = lane >> 2, tq = lane & 3;

    if (t < 128) BS[t] = b[t];
    for (int i = t; i < 128 * (XSTR - BB); i += 256) {       // zero pad cols once
        int r = i / (XSTR - BB), k = BB + (i - r * (XSTR - BB));
        XS[r * XSTR + k] = __float2half(0.f);
    }

    uint32_t xsb = smem_u32(XS);
    int rrow = w * 16 + (lane & 15);
    int coff = (lane >> 4) * 8;

    float ls[4] = {0.f, 0.f, 0.f, 0.f};
    float lq[4] = {0.f, 0.f, 0.f, 0.f};

    for (int ti = 0; ti < TPB; ti++) {
        int tile = blockIdx.x * TPB + ti;
        int p0 = tile * 128;
        int n0 = p0 / MMN;
        __syncthreads();
        // stage X tile (fp16), P rows, idx
        for (int e = t; e < 128 * BB; e += 256) {
            int r = e / BB, k = e - r * BB;
            long gi = (long)p0 * BB + e;
            float v = (gi < (long)PAIRS * BB) ? nbr[gi] : 0.f;
            XS[r * XSTR + k] = __float2half_rn(v);
        }
        for (int i = t; i < 12 * 128; i += 256) {
            int r = i >> 7, c = i & 127;
            int n = n0 + r;
            PS[r * 132 + c] = (n < NN) ? d_PQ[n * 256 + c] : 0.f;
        }
        if (t < 128) JS[t] = (p0 + t < PAIRS) ? idx[p0 + t] : 0;
        __syncthreads();

        // ---- pass 1: mma, add P + b, STS into GO ----
        uint32_t a[3][4];
#pragma unroll
        for (int ks = 0; ks < 3; ks++) {
            uint32_t addr = xsb + (uint32_t)(rrow * XSTR + ks * 16 + coff) * 2;
            asm volatile("ldmatrix.sync.aligned.m8n8.x4.shared.b16 {%0,%1,%2,%3}, [%4];"
                         : "=r"(a[ks][0]), "=r"(a[ks][1]), "=r"(a[ks][2]), "=r"(a[ks][3])
                         : "r"(addr));
        }
        int pr0 = w * 16 + g;                 // local pair rows
        int pr1 = pr0 + 8;
        int rp0 = (p0 + pr0) / MMN - n0;      // P row indices within PS
        int rp1 = (p0 + pr1) / MMN - n0;

#pragma unroll 4
        for (int nt = 0; nt < 16; nt++) {
            float c0 = 0.f, c1 = 0.f, c2 = 0.f, c3 = 0.f;
#pragma unroll
            for (int ks = 0; ks < 3; ks++) {
                uint2 bf = d_Bf[(ks * 16 + nt) * 32 + lane];
                asm volatile(
                    "mma.sync.aligned.m16n8k16.row.col.f32.f16.f16.f32 "
                    "{%0,%1,%2,%3}, {%4,%5,%6,%7}, {%8,%9}, {%0,%1,%2,%3};"
                    : "+f"(c0), "+f"(c1), "+f"(c2), "+f"(c3)
                    : "r"(a[ks][0]), "r"(a[ks][1]), "r"(a[ks][2]), "r"(a[ks][3]),
                      "r"(bf.x), "r"(bf.y));
            }
            int ch = nt * 8 + 2 * tq;
            float2 bv  = *(const float2*)&BS[ch];
            float2 pv0 = *(const float2*)&PS[rp0 * 132 + ch];
            float2 pv1 = *(const float2*)&PS[rp1 * 132 + ch];
            *(float2*)&GO[pr0 * 132 + ch] = make_float2(c0 + pv0.x + bv.x, c1 + pv0.y + bv.y);
            *(float2*)&GO[pr1 * 132 + ch] = make_float2(c2 + pv1.x + bv.x, c3 + pv1.y + bv.y);
        }
        __syncthreads();

        // ---- pass 2: GO + Q -> d_gh (coalesced), BN1 stats ----
#pragma unroll
        for (int i = 0; i < 16; i++) {
            int p  = w * 16 + i;
            int pi = p0 + p;
            if (pi >= PAIRS) break;
            int j = JS[p];
            float4 gv = *(const float4*)&GO[p * 132 + 4 * lane];
            float4 qv = *(const float4*)&d_PQ[(long)j * 256 + 128 + 4 * lane];
            float g0 = gv.x + qv.x, g1 = gv.y + qv.y;
            float g2 = gv.z + qv.z, g3 = gv.w + qv.w;
            uint2 st;
            __half2 h01 = __floats2half2_rn(g0, g1);
            __half2 h23 = __floats2half2_rn(g2, g3);
            st.x = *reinterpret_cast<uint32_t*>(&h01);
            st.y = *reinterpret_cast<uint32_t*>(&h23);
            *(uint2*)&d_gh[(long)pi * 64 + 2 * lane] = st;
            ls[0] += g0; ls[1] += g1; ls[2] += g2; ls[3] += g3;
            lq[0] += g0 * g0; lq[1] += g1 * g1; lq[2] += g2 * g2; lq[3] += g3 * g3;
        }
    }
    int slot = (blockIdx.x * 8 + w) & 63;
#pragma unroll
    for (int k = 0; k < 4; k++) {
        atomicAdd(&d_p1s[slot][4 * lane + k], ls[k]);
        atomicAdd(&d_p1q[slot][4 * lane + k], lq[k]);
    }
}

// ---------------- K3b: finalize BN1 stats ----------------
__global__ void k_fin1() {
    int t = threadIdx.x;                 // 256
    int ch = t >> 1, h = t & 1;
    float s = 0.f, q = 0.f;
#pragma unroll
    for (int i = 0; i < 32; i++) { s += d_p1s[h * 32 + i][ch]; q += d_p1q[h * 32 + i][ch]; }
    s += __shfl_xor_sync(0xffffffffu, s, 1);
    q += __shfl_xor_sync(0xffffffffu, q, 1);
    if (!h) { d_s1[ch] = s; d_q1[ch] = q; }
}

// ---------------- K4: BN1 + sigmoid*softplus + sum over m + BN2 partials ----
#define GRID4 1480
__global__ __launch_bounds__(256) void k_reduce(const float* __restrict__ g1,
                                                const float* __restrict__ b1) {
    int t = threadIdx.x;
    int u = t & 31, sub = t >> 5;
    int a0 = 2 * u;

    float inv = 1.f / (float)PAIRS;
    float mf0 = d_s1[a0] * inv,      mf1 = d_s1[a0 + 1] * inv;
    float vf0 = d_q1[a0] * inv - mf0 * mf0;
    float vf1 = d_q1[a0 + 1] * inv - mf1 * mf1;
    float sf0 = rsqrtf(vf0 + BN_EPS) * g1[a0];
    float sf1 = rsqrtf(vf1 + BN_EPS) * g1[a0 + 1];
    float tf0 = b1[a0] - mf0 * sf0,  tf1 = b1[a0 + 1] - mf1 * sf1;

    float mc0 = d_s1[64 + a0] * inv, mc1 = d_s1[65 + a0] * inv;
    float vc0 = d_q1[64 + a0] * inv - mc0 * mc0;
    float vc1 = d_q1[65 + a0] * inv - mc1 * mc1;
    float sc0 = rsqrtf(vc0 + BN_EPS) * g1[64 + a0];
    float sc1 = rsqrtf(vc1 + BN_EPS) * g1[65 + a0];
    float tc0 = b1[64 + a0] - mc0 * sc0, tc1 = b1[65 + a0] - mc1 * sc1;

    float ls0 = 0.f, ls1 = 0.f, lq0 = 0.f, lq1 = 0.f;
    for (int n = blockIdx.x * 8 + sub; n < NN; n += gridDim.x * 8) {
        const __half2* gp = &d_gh[(long)n * 12 * 64];
        float acc0 = 0.f, acc1 = 0.f;
#pragma unroll
        for (int m = 0; m < 12; m++) {
            float2 xf = __half22float2(gp[m * 64 + u]);
            float2 xc = __half22float2(gp[m * 64 + 32 + u]);
            float f0 = xf.x * sf0 + tf0, f1 = xf.y * sf1 + tf1;
            float c0v = xc.x * sc0 + tc0, c1v = xc.y * sc1 + tc1;
            float sg0 = 0.5f * tanh_ap(0.5f * f0) + 0.5f;
            float sg1 = 0.5f * tanh_ap(0.5f * f1) + 0.5f;
            float sp0 = fmaxf(c0v, 0.f) + __logf(1.f + __expf(-fabsf(c0v)));
            float sp1 = fmaxf(c1v, 0.f) + __logf(1.f + __expf(-fabsf(c1v)));
            acc0 += sg0 * sp0;
            acc1 += sg1 * sp1;
        }
        *(float2*)&d_ns[n * 64 + a0] = make_float2(acc0, acc1);
        ls0 += acc0; lq0 += acc0 * acc0;
        ls1 += acc1; lq1 += acc1 * acc1;
    }
    int slot = blockIdx.x & 31;
    atomicAdd(&d_p2s[slot][a0],     ls0);
    atomicAdd(&d_p2s[slot][a0 + 1], ls1);
    atomicAdd(&d_p2q[slot][a0],     lq0);
    atomicAdd(&d_p2q[slot][a0 + 1], lq1);
}

// ---------------- K5: finalize BN2 stats ----------------
__global__ void k_fin2() {
    int t = threadIdx.x;                 // 256
    int ch = t >> 2, qd = t & 3;
    float s = 0.f, q = 0.f;
#pragma unroll
    for (int i = 0; i < 8; i++) { s += d_p2s[qd * 8 + i][ch]; q += d_p2q[qd * 8 + i][ch]; }
    s += __shfl_xor_sync(0xffffffffu, s, 1);
    q += __shfl_xor_sync(0xffffffffu, q, 1);
    s += __shfl_xor_sync(0xffffffffu, s, 2);
    q += __shfl_xor_sync(0xffffffffu, q, 2);
    if (qd == 0) { d_s2[ch] = s; d_q2[ch] = q; }
}

// ---------------- K6: BN2 + residual + softplus -> out ----------------------
__global__ __launch_bounds__(256) void k_out(const float* __restrict__ atom,
                                             const float* __restrict__ g2,
                                             const float* __restrict__ b2,
                                             float* __restrict__ out) {
    int i = blockIdx.x * blockDim.x + threadIdx.x;
    if (i >= NN * 64) return;
    int a = i & 63;
    float inv = 1.f / (float)NN;
    float m = d_s2[a] * inv;
    float v = d_q2[a] * inv - m * m;
    float s = rsqrtf(v + BN_EPS) * g2[a];
    float tt = b2[a] - m * s;
    float x = atom[i] + d_ns[i] * s + tt;
    out[i] = fmaxf(x, 0.f) + __logf(1.f + __expf(-fabsf(x)));
}

// ---------------- launch ------------------------------------------------------
extern "C" void kernel_launch(void* const* d_in, const int* in_sizes, int n_in,
                              void* d_out, int out_size) {
    const float* atom = (const float*)d_in[0];   // (N, 64)
    const float* nbr  = (const float*)d_in[1];   // (N, 12, 41)
    const int*   idx  = (const int*)  d_in[2];   // (N, 12)
    const float* W    = (const float*)d_in[3];   // (128, 169)
    const float* b    = (const float*)d_in[4];   // (128,)
    const float* g1   = (const float*)d_in[5];
    const float* b1   = (const float*)d_in[6];
    const float* g2   = (const float*)d_in[7];
    const float* b2   = (const float*)d_in[8];
    float* out = (float*)d_out;

    cudaFuncSetAttribute(k_main, cudaFuncAttributeMaxDynamicSharedMemorySize, SM_TOT);

    kzero   <<<16, 512>>>();
    k_bfrag <<<6, 256>>>(W);
    k_bfrag2<<<16, 256>>>(W);
    k_pq    <<<(NN + 127) / 128, 256>>>(atom);
    k_main  <<<GRIDM, 256, SM_TOT>>>(nbr, idx, b);
    k_fin1  <<<1, 256>>>();
    k_reduce<<<GRID4, 256>>>(g1, b1);
    k_fin2  <<<1, 256>>>();
    k_out   <<<(NN * 64 + 255) / 256, 256>>>(atom, g2, b2, out);
}

// round 17
// speedup vs baseline: 2.4340x; 1.1017x over previous
#include <cuda_runtime.h>
#include <cuda_fp16.h>
#include <cstdint>

// Problem constants (fixed shapes)
#define NN    50000
#define MMN   12
#define AA    64
#define BB    41
#define FF    169
#define OO    128
#define PAIRS (NN*MMN)     // 600000
#define BN_EPS 1e-5f

#define XSTR  56           // smem row stride in halfs (112B, 16B-aligned rows)
#define TPB   4            // tiles (128 pairs) per block
#define GRIDM 1172         // 1172*4 = 4688 tiles >= ceil(600000/128)

// dynamic smem layout for k_main (bytes)
#define SM_XS   0                       // 128*56 halfs          = 14336
#define SM_GO   14336                   // 128*68 uint (half2)   = 34816
#define SM_PS   49152                   // 12*132 f32            = 6336
#define SM_BS   55488                   // 128 f32               = 512
#define SM_JS   56000                   // 128 int               = 512
#define SM_TOT  56512

// ---------------- scratch (device globals) ----------------
__device__ __align__(16) float   d_PQ[NN * 256];               // [n][o<128]=P, [n][128+o]=Q
__device__ __align__(16) __half2 d_gh[(long)PAIRS * 64];       // g as half2 (channel pairs)
__device__ __align__(16) float   d_ns[NN * AA];
__device__ __align__(16) float   d_s1[OO], d_q1[OO];
__device__ __align__(16) float   d_s2[AA], d_q2[AA];
__device__ __align__(16) float   d_p1s[64][OO], d_p1q[64][OO]; // BN1 partial slots
__device__ __align__(16) float   d_p2s[32][AA], d_p2q[32][AA]; // BN2 partial slots
__device__ __align__(16) uint2   d_Bf[3 * 16 * 32];            // W3 B-fragments (k_main)
__device__ __align__(16) uint2   d_Bf2[4 * 32 * 32];           // W12 B-fragments (k_pq)

// ---------------- helpers ----------------
__device__ __forceinline__ float tanh_ap(float x) {
    float y; asm("tanh.approx.f32 %0, %1;" : "=f"(y) : "f"(x)); return y;
}
__device__ __forceinline__ uint32_t smem_u32(const void* p) {
    uint32_t a;
    asm("{ .reg .u64 t; cvta.to.shared.u64 t, %1; cvt.u32.u64 %0, t; }" : "=r"(a) : "l"(p));
    return a;
}

// ---------------- K0: zero partial-stat slots ----------------
__global__ void kzero() {
    int i = blockIdx.x * blockDim.x + threadIdx.x;
    if (i < 64 * OO) { (&d_p1s[0][0])[i] = 0.f; (&d_p1q[0][0])[i] = 0.f; }
    if (i < 32 * AA) { (&d_p2s[0][0])[i] = 0.f; (&d_p2q[0][0])[i] = 0.f; }
}

// ---------------- K0b: W3 B-fragments (nbr GEMM), lane-indexed --------------
__global__ void k_bfrag(const float* __restrict__ W) {
    int e = blockIdx.x * blockDim.x + threadIdx.x;
    if (e >= 3 * 16 * 32) return;
    int lane = e & 31, nt = (e >> 5) & 15, ks = e >> 9;
    int g = lane >> 2, tq = lane & 3;
    int ch = nt * 8 + g;
    int k0 = ks * 16 + 2 * tq;
    float w0 = (k0     < BB) ? W[ch * FF + 128 + k0]     : 0.f;
    float w1 = (k0 + 1 < BB) ? W[ch * FF + 128 + k0 + 1] : 0.f;
    float w8 = (k0 + 8 < BB) ? W[ch * FF + 128 + k0 + 8] : 0.f;
    float w9 = (k0 + 9 < BB) ? W[ch * FF + 128 + k0 + 9] : 0.f;
    __half2 b01 = __floats2half2_rn(w0, w1);
    __half2 b23 = __floats2half2_rn(w8, w9);
    uint2 v;
    v.x = *reinterpret_cast<uint32_t*>(&b01);
    v.y = *reinterpret_cast<uint32_t*>(&b23);
    d_Bf[e] = v;
}

// ---------------- K0c: W12 B-fragments (PQ GEMM, N=256, K=64) ---------------
__global__ void k_bfrag2(const float* __restrict__ W) {
    int e = blockIdx.x * blockDim.x + threadIdx.x;
    if (e >= 4 * 32 * 32) return;
    int lane = e & 31, nt = (e >> 5) & 31, ks = e >> 10;
    int g = lane >> 2, tq = lane & 3;
    int n = nt * 8 + g;
    int k0 = ks * 16 + 2 * tq;
    const float* src = (n < 128) ? &W[n * FF] : &W[(n - 128) * FF + 64];
    __half2 b01 = __floats2half2_rn(src[k0],     src[k0 + 1]);
    __half2 b23 = __floats2half2_rn(src[k0 + 8], src[k0 + 9]);
    uint2 v;
    v.x = *reinterpret_cast<uint32_t*>(&b01);
    v.y = *reinterpret_cast<uint32_t*>(&b23);
    d_Bf2[e] = v;
}

// ---------------- K1: PQ = atom @ [W1;W2]^T via HMMA (N x 256, K=64) --------
#define ASTR 72   // 144B rows, 16B-aligned
__global__ __launch_bounds__(256) void k_pq(const float* __restrict__ atom) {
    __shared__ __align__(16) __half AS[128 * ASTR];
    int t = threadIdx.x, w = t >> 5, lane = t & 31;
    int g = lane >> 2, tq = lane & 3;
    int row0 = blockIdx.x * 128;

    for (int e = t; e < 128 * 64; e += 256) {
        int r = e >> 6, k = e & 63;
        float v = (row0 + r < NN) ? atom[(row0 + r) * 64 + k] : 0.f;
        AS[r * ASTR + k] = __float2half_rn(v);
    }
    __syncthreads();

    uint32_t asb = smem_u32(AS);
    int rrow = w * 16 + (lane & 15);
    int coff = (lane >> 4) * 8;

    uint32_t a[4][4];
#pragma unroll
    for (int ks = 0; ks < 4; ks++) {
        uint32_t addr = asb + (uint32_t)(rrow * ASTR + ks * 16 + coff) * 2;
        asm volatile("ldmatrix.sync.aligned.m8n8.x4.shared.b16 {%0,%1,%2,%3}, [%4];"
                     : "=r"(a[ks][0]), "=r"(a[ks][1]), "=r"(a[ks][2]), "=r"(a[ks][3])
                     : "r"(addr));
    }

    int r0 = row0 + w * 16 + g;
    int r1 = r0 + 8;
#pragma unroll 4
    for (int nt = 0; nt < 32; nt++) {
        float c0 = 0.f, c1 = 0.f, c2 = 0.f, c3 = 0.f;
#pragma unroll
        for (int ks = 0; ks < 4; ks++) {
            uint2 bf = d_Bf2[(ks * 32 + nt) * 32 + lane];
            asm volatile(
                "mma.sync.aligned.m16n8k16.row.col.f32.f16.f16.f32 "
                "{%0,%1,%2,%3}, {%4,%5,%6,%7}, {%8,%9}, {%0,%1,%2,%3};"
                : "+f"(c0), "+f"(c1), "+f"(c2), "+f"(c3)
                : "r"(a[ks][0]), "r"(a[ks][1]), "r"(a[ks][2]), "r"(a[ks][3]),
                  "r"(bf.x), "r"(bf.y));
        }
        int ch = nt * 8 + 2 * tq;
        if (r0 < NN) *(float2*)&d_PQ[r0 * 256 + ch] = make_float2(c0, c1);
        if (r1 < NN) *(float2*)&d_PQ[r1 * 256 + ch] = make_float2(c2, c3);
    }
}

// ---------------- K2: main GEMM (HMMA) + coalesced epilogue + BN1 stats -----
__global__ __launch_bounds__(256) void k_main(const float* __restrict__ nbr,
                                              const int*   __restrict__ idx,
                                              const float* __restrict__ b) {
    extern __shared__ __align__(16) char smem[];
    __half*   XS = (__half*)  (smem + SM_XS);
    uint32_t* GO = (uint32_t*)(smem + SM_GO);   // half2 per slot, stride 68
    float*    PS = (float*)   (smem + SM_PS);
    float*    BS = (float*)   (smem + SM_BS);
    int*      JS = (int*)     (smem + SM_JS);

    int t = threadIdx.x, w = t >> 5, lane = t & 31;
    int g = lane >> 2, tq = lane & 3;

    if (t < 128) BS[t] = b[t];
    for (int i = t; i < 128 * (XSTR - BB); i += 256) {       // zero pad cols once
        int r = i / (XSTR - BB), k = BB + (i - r * (XSTR - BB));
        XS[r * XSTR + k] = __float2half(0.f);
    }

    uint32_t xsb = smem_u32(XS);
    int rrow = w * 16 + (lane & 15);
    int coff = (lane >> 4) * 8;

    float ls[4] = {0.f, 0.f, 0.f, 0.f};
    float lq[4] = {0.f, 0.f, 0.f, 0.f};

    for (int ti = 0; ti < TPB; ti++) {
        int tile = blockIdx.x * TPB + ti;
        int p0 = tile * 128;
        int n0 = p0 / MMN;
        __syncthreads();
        // stage X tile (fp16), P rows, idx
        for (int e = t; e < 128 * BB; e += 256) {
            int r = e / BB, k = e - r * BB;
            long gi = (long)p0 * BB + e;
            float v = (gi < (long)PAIRS * BB) ? nbr[gi] : 0.f;
            XS[r * XSTR + k] = __float2half_rn(v);
        }
        for (int i = t; i < 12 * 128; i += 256) {
            int r = i >> 7, c = i & 127;
            int n = n0 + r;
            PS[r * 132 + c] = (n < NN) ? d_PQ[n * 256 + c] : 0.f;
        }
        if (t < 128) JS[t] = (p0 + t < PAIRS) ? idx[p0 + t] : 0;
        __syncthreads();

        // ---- pass 1: mma, add P + b, store half2 into GO (conflict-free) ----
        uint32_t a[3][4];
#pragma unroll
        for (int ks = 0; ks < 3; ks++) {
            uint32_t addr = xsb + (uint32_t)(rrow * XSTR + ks * 16 + coff) * 2;
            asm volatile("ldmatrix.sync.aligned.m8n8.x4.shared.b16 {%0,%1,%2,%3}, [%4];"
                         : "=r"(a[ks][0]), "=r"(a[ks][1]), "=r"(a[ks][2]), "=r"(a[ks][3])
                         : "r"(addr));
        }
        int pr0 = w * 16 + g;                 // local pair rows
        int pr1 = pr0 + 8;
        int rp0 = (p0 + pr0) / MMN - n0;      // P row indices within PS
        int rp1 = (p0 + pr1) / MMN - n0;

#pragma unroll 4
        for (int nt = 0; nt < 16; nt++) {
            float c0 = 0.f, c1 = 0.f, c2 = 0.f, c3 = 0.f;
#pragma unroll
            for (int ks = 0; ks < 3; ks++) {
                uint2 bf = d_Bf[(ks * 16 + nt) * 32 + lane];
                asm volatile(
                    "mma.sync.aligned.m16n8k16.row.col.f32.f16.f16.f32 "
                    "{%0,%1,%2,%3}, {%4,%5,%6,%7}, {%8,%9}, {%0,%1,%2,%3};"
                    : "+f"(c0), "+f"(c1), "+f"(c2), "+f"(c3)
                    : "r"(a[ks][0]), "r"(a[ks][1]), "r"(a[ks][2]), "r"(a[ks][3]),
                      "r"(bf.x), "r"(bf.y));
            }
            int ch = nt * 8 + 2 * tq;
            float2 bv  = *(const float2*)&BS[ch];
            float2 pv0 = *(const float2*)&PS[rp0 * 132 + ch];
            float2 pv1 = *(const float2*)&PS[rp1 * 132 + ch];
            __half2 h0 = __floats2half2_rn(c0 + pv0.x + bv.x, c1 + pv0.y + bv.y);
            __half2 h1 = __floats2half2_rn(c2 + pv1.x + bv.x, c3 + pv1.y + bv.y);
            int col = nt * 4 + tq;
            GO[pr0 * 68 + col] = *reinterpret_cast<uint32_t*>(&h0);
            GO[pr1 * 68 + col] = *reinterpret_cast<uint32_t*>(&h1);
        }
        __syncthreads();

        // ---- pass 2: GO + Q -> d_gh (coalesced), BN1 stats; MLP=4 batches ----
#pragma unroll
        for (int grp = 0; grp < 4; grp++) {
            float4 qv[4];
            uint2  gv[4];
#pragma unroll
            for (int i = 0; i < 4; i++) {
                int p = w * 16 + grp * 4 + i;
                int j = JS[p];
                qv[i] = *(const float4*)&d_PQ[(long)j * 256 + 128 + 4 * lane];
                gv[i] = *(const uint2*)&GO[p * 68 + 2 * lane];
            }
#pragma unroll
            for (int i = 0; i < 4; i++) {
                int p  = w * 16 + grp * 4 + i;
                int pi = p0 + p;
                float2 f01 = __half22float2(*reinterpret_cast<__half2*>(&gv[i].x));
                float2 f23 = __half22float2(*reinterpret_cast<__half2*>(&gv[i].y));
                float g0 = f01.x + qv[i].x, g1 = f01.y + qv[i].y;
                float g2 = f23.x + qv[i].z, g3 = f23.y + qv[i].w;
                if (pi < PAIRS) {
                    __half2 o01 = __floats2half2_rn(g0, g1);
                    __half2 o23 = __floats2half2_rn(g2, g3);
                    uint2 st;
                    st.x = *reinterpret_cast<uint32_t*>(&o01);
                    st.y = *reinterpret_cast<uint32_t*>(&o23);
                    *(uint2*)&d_gh[(long)pi * 64 + 2 * lane] = st;
                    ls[0] += g0; ls[1] += g1; ls[2] += g2; ls[3] += g3;
                    lq[0] += g0 * g0; lq[1] += g1 * g1;
                    lq[2] += g2 * g2; lq[3] += g3 * g3;
                }
            }
        }
    }
    int slot = (blockIdx.x * 8 + w) & 63;
#pragma unroll
    for (int k = 0; k < 4; k++) {
        atomicAdd(&d_p1s[slot][4 * lane + k], ls[k]);
        atomicAdd(&d_p1q[slot][4 * lane + k], lq[k]);
    }
}

// ---------------- K3b: finalize BN1 stats ----------------
__global__ void k_fin1() {
    int t = threadIdx.x;                 // 256
    int ch = t >> 1, h = t & 1;
    float s = 0.f, q = 0.f;
#pragma unroll
    for (int i = 0; i < 32; i++) { s += d_p1s[h * 32 + i][ch]; q += d_p1q[h * 32 + i][ch]; }
    s += __shfl_xor_sync(0xffffffffu, s, 1);
    q += __shfl_xor_sync(0xffffffffu, q, 1);
    if (!h) { d_s1[ch] = s; d_q1[ch] = q; }
}

// ---------------- K4: BN1 + sigmoid*softplus + sum over m + BN2 partials ----
// Thread owns 4 filter + 4 core channels (uint2 loads); 16 n per block;
// grid covers all n in one shot (no loop).
#define GRID4 3125
__global__ __launch_bounds__(256) void k_reduce(const float* __restrict__ g1,
                                                const float* __restrict__ b1) {
    int t = threadIdx.x;
    int u = t & 15, sub = t >> 4;
    int a0 = 4 * u;

    float inv = 1.f / (float)PAIRS;
    float sf[4], tf[4], sc[4], tc[4];
#pragma unroll
    for (int k = 0; k < 4; k++) {
        float mf = d_s1[a0 + k] * inv;
        float vf = d_q1[a0 + k] * inv - mf * mf;
        sf[k] = rsqrtf(vf + BN_EPS) * g1[a0 + k];
        tf[k] = b1[a0 + k] - mf * sf[k];
        float mc = d_s1[64 + a0 + k] * inv;
        float vc = d_q1[64 + a0 + k] * inv - mc * mc;
        sc[k] = rsqrtf(vc + BN_EPS) * g1[64 + a0 + k];
        tc[k] = b1[64 + a0 + k] - mc * sc[k];
    }

    int n = blockIdx.x * 16 + sub;
    const __half2* gp = &d_gh[(long)n * 12 * 64];

    float acc[4] = {0.f, 0.f, 0.f, 0.f};
#pragma unroll
    for (int m = 0; m < 12; m++) {
        uint2 fv = *(const uint2*)&gp[m * 64 + 2 * u];
        uint2 cv = *(const uint2*)&gp[m * 64 + 32 + 2 * u];
        float2 f01 = __half22float2(*reinterpret_cast<__half2*>(&fv.x));
        float2 f23 = __half22float2(*reinterpret_cast<__half2*>(&fv.y));
        float2 c01 = __half22float2(*reinterpret_cast<__half2*>(&cv.x));
        float2 c23 = __half22float2(*reinterpret_cast<__half2*>(&cv.y));
        float f[4] = {f01.x, f01.y, f23.x, f23.y};
        float c[4] = {c01.x, c01.y, c23.x, c23.y};
#pragma unroll
        for (int k = 0; k < 4; k++) {
            float xf = f[k] * sf[k] + tf[k];
            float xc = c[k] * sc[k] + tc[k];
            float sg = 0.5f * tanh_ap(0.5f * xf) + 0.5f;
            float sp = fmaxf(xc, 0.f) + __logf(1.f + __expf(-fabsf(xc)));
            acc[k] += sg * sp;
        }
    }
    *(float4*)&d_ns[n * 64 + a0] = make_float4(acc[0], acc[1], acc[2], acc[3]);

    int slot = blockIdx.x & 31;
#pragma unroll
    for (int k = 0; k < 4; k++) {
        atomicAdd(&d_p2s[slot][a0 + k], acc[k]);
        atomicAdd(&d_p2q[slot][a0 + k], acc[k] * acc[k]);
    }
}

// ---------------- K5: finalize BN2 stats ----------------
__global__ void k_fin2() {
    int t = threadIdx.x;                 // 256
    int ch = t >> 2, qd = t & 3;
    float s = 0.f, q = 0.f;
#pragma unroll
    for (int i = 0; i < 8; i++) { s += d_p2s[qd * 8 + i][ch]; q += d_p2q[qd * 8 + i][ch]; }
    s += __shfl_xor_sync(0xffffffffu, s, 1);
    q += __shfl_xor_sync(0xffffffffu, q, 1);
    s += __shfl_xor_sync(0xffffffffu, s, 2);
    q += __shfl_xor_sync(0xffffffffu, q, 2);
    if (qd == 0) { d_s2[ch] = s; d_q2[ch] = q; }
}

// ---------------- K6: BN2 + residual + softplus -> out ----------------------
__global__ __launch_bounds__(256) void k_out(const float* __restrict__ atom,
                                             const float* __restrict__ g2,
                                             const float* __restrict__ b2,
                                             float* __restrict__ out) {
    int i = blockIdx.x * blockDim.x + threadIdx.x;
    if (i >= NN * 64) return;
    int a = i & 63;
    float inv = 1.f / (float)NN;
    float m = d_s2[a] * inv;
    float v = d_q2[a] * inv - m * m;
    float s = rsqrtf(v + BN_EPS) * g2[a];
    float tt = b2[a] - m * s;
    float x = atom[i] + d_ns[i] * s + tt;
    out[i] = fmaxf(x, 0.f) + __logf(1.f + __expf(-fabsf(x)));
}

// ---------------- launch ------------------------------------------------------
extern "C" void kernel_launch(void* const* d_in, const int* in_sizes, int n_in,
                              void* d_out, int out_size) {
    const float* atom = (const float*)d_in[0];   // (N, 64)
    const float* nbr  = (const float*)d_in[1];   // (N, 12, 41)
    const int*   idx  = (const int*)  d_in[2];   // (N, 12)
    const float* W    = (const float*)d_in[3];   // (128, 169)
    const float* b    = (const float*)d_in[4];   // (128,)
    const float* g1   = (const float*)d_in[5];
    const float* b1   = (const float*)d_in[6];
    const float* g2   = (const float*)d_in[7];
    const float* b2   = (const float*)d_in[8];
    float* out = (float*)d_out;

    cudaFuncSetAttribute(k_main, cudaFuncAttributeMaxDynamicSharedMemorySize, SM_TOT);

    kzero   <<<16, 512>>>();
    k_bfrag <<<6, 256>>>(W);
    k_bfrag2<<<16, 256>>>(W);
    k_pq    <<<(NN + 127) / 128, 256>>>(atom);
    k_main  <<<GRIDM, 256, SM_TOT>>>(nbr, idx, b);
    k_fin1  <<<1, 256>>>();
    k_reduce<<<GRID4, 256>>>(g1, b1);
    k_fin2  <<<1, 256>>>();
    k_out   <<<(NN * 64 + 255) / 256, 256>>>(atom, g2, b2, out);
}